// round 2
// baseline (speedup 1.0000x reference)
#include <cuda_runtime.h>

#define Bn   8
#define Hn   512
#define Wn   512
#define HWn  (Hn*Wn)        // 262144
#define NPIX (Bn*HWn)       // 2097152
#define NBC  24             // B*3 (b,c) pairs
#define NBINS 4096
#define RMAX 50
#define MAXWP (Wn + 2*RMAX) // 612

// ---------------- scratch (no allocation allowed: __device__ globals) -------
__device__ float g_t0[NPIX];
__device__ float g_gray[NPIX];
__device__ float g_tg[NPIX];
__device__ float g_h0[NPIX];
__device__ float g_h1[NPIX];
__device__ float g_h2[NPIX];
__device__ float g_h3[NPIX];
__device__ float g_a[NPIX];
__device__ float g_b[NPIX];
__device__ float g_J[3*NPIX];
__device__ unsigned int g_hist[NBC*NBINS];
__device__ unsigned int g_sub[NBC*2*NBINS];
__device__ int   g_seld[NBC*4];   // binL, rankL, binH, rankH
__device__ float g_p[NBC*2];      // p_low, p_high per (b,c)

__device__ __forceinline__ int reflW(int j){ j = j < 0 ? -j : j; return j >= Wn ? 2*Wn - 2 - j : j; }
__device__ __forceinline__ int reflH(int j){ j = j < 0 ? -j : j; return j >= Hn ? 2*Hn - 2 - j : j; }
__device__ __forceinline__ int get_r(const int* rp){ int r = rp[0]; if (r < 1) r = 1; if (r > RMAX) r = RMAX; return r; }

// ---------------- K1: t0 + gray (pointwise) --------------------------------
__global__ void k_t0gray(const float* __restrict__ img,
                         const float* __restrict__ omega,
                         const float* __restrict__ atm)
{
    int idx = blockIdx.x * blockDim.x + threadIdx.x;
    if (idx >= NPIX) return;
    int b = idx >> 18;
    int pix = idx & (HWn - 1);
    const float* ib = img + (size_t)b * 3 * HWn + pix;
    float i0 = ib[0], i1 = ib[HWn], i2 = ib[2*HWn];
    float a0 = atm[b*3+0], a1 = atm[b*3+1], a2 = atm[b*3+2];
    float d0 = i0 / (a0 + 1e-8f);
    float d1 = i1 / (a1 + 1e-8f);
    float d2 = i2 / (a2 + 1e-8f);
    float dark = fminf(d0, fminf(d1, d2));
    g_t0[idx]   = 1.0f - omega[b] * dark;
    g_gray[idx] = 0.299f*i0 + 0.587f*i1 + 0.114f*i2;
}

// ---------------- K2: gradient-constrained tg ------------------------------
__global__ void k_tg()
{
    int idx = blockIdx.x * blockDim.x + threadIdx.x;
    if (idx >= NPIX) return;
    int b = idx >> 18;
    int pix = idx & (HWn - 1);
    int y = pix >> 9, x = pix & 511;
    int base = b << 18;
    int yy = (y > 0) ? (y - 1) : 0;
    float t_yy_x = g_t0[base + (yy << 9) + x];
    float txv;
    if (x == 0) {
        txv = t_yy_x;
    } else {
        float t_yy_xm1 = g_t0[base + (yy << 9) + x - 1];
        txv = t_yy_xm1 * expf(-fabsf(t_yy_x - t_yy_xm1));
    }
    float tgv;
    if (y == 0) {
        tgv = txv;
    } else {
        float t_y_x = g_t0[base + (y << 9) + x];
        tgv = txv * expf(-fabsf(t_y_x - t_yy_x));
    }
    g_tg[idx] = tgv;
}

// ---------------- K3: horizontal box (4 fields fused, prefix in shared) ----
__global__ void k_hbox4(const int* __restrict__ rp)
{
    int r = get_r(rp);
    int Wp = Wn + 2*r;
    int row = blockIdx.x;
    int b = row >> 9, y = row & 511;
    int base = (b << 18) + (y << 9);
    int tid = threadIdx.x;

    __shared__ float4 v[MAXWP];
    for (int i = tid; i < Wp; i += blockDim.x) {
        int j = reflW(i - r);
        float g = g_gray[base + j];
        float t = g_tg[base + j];
        v[i] = make_float4(g, t, g*t, g*g);
    }
    __syncthreads();
    for (int d = 1; d < Wp; d <<= 1) {
        float4 add;
        bool act = (tid < Wp) && (tid >= d);
        if (act) add = v[tid - d];
        __syncthreads();
        if (act) {
            float4 c = v[tid];
            v[tid] = make_float4(c.x+add.x, c.y+add.y, c.z+add.z, c.w+add.w);
        }
        __syncthreads();
    }
    if (tid < Wn) {
        float4 s1 = v[tid + 2*r];
        float4 s0 = (tid > 0) ? v[tid - 1] : make_float4(0.f,0.f,0.f,0.f);
        g_h0[base+tid] = s1.x - s0.x;
        g_h1[base+tid] = s1.y - s0.y;
        g_h2[base+tid] = s1.z - s0.z;
        g_h3[base+tid] = s1.w - s0.w;
    }
}

// ---------------- K4: vertical box (4 fields) + a,b ------------------------
__global__ void k_vbox_ab(const int* __restrict__ rp)
{
    int r = get_r(rp);
    float invk2 = 1.0f / (float)((2*r+1)*(2*r+1));
    int t = blockIdx.x * blockDim.x + threadIdx.x;
    if (t >= Bn * Wn * 8) return;
    int x   = t & 511;
    int seg = (t >> 9) & 7;
    int b   = t >> 12;
    int base = b << 18;
    int y0 = seg << 6;

    float s0 = 0.f, s1 = 0.f, s2 = 0.f, s3 = 0.f;
    for (int d = -r; d <= r; d++) {
        int j = reflH(y0 + d);
        int o = base + (j << 9) + x;
        s0 += g_h0[o]; s1 += g_h1[o]; s2 += g_h2[o]; s3 += g_h3[o];
    }
    for (int yy = 0; yy < 64; yy++) {
        int y = y0 + yy;
        int o = base + (y << 9) + x;
        float mI  = s0 * invk2, mp = s1 * invk2;
        float mIp = s2 * invk2, mII = s3 * invk2;
        float a  = (mIp - mI*mp) / (mII - mI*mI + 0.5f);
        float bb = mp - a * mI;
        g_a[o] = a;
        g_b[o] = bb;
        if (yy < 63) {
            int ja = reflH(y + 1 + r);
            int js = reflH(y - r);
            int oa = base + (ja << 9) + x;
            int os = base + (js << 9) + x;
            s0 += g_h0[oa] - g_h0[os];
            s1 += g_h1[oa] - g_h1[os];
            s2 += g_h2[oa] - g_h2[os];
            s3 += g_h3[oa] - g_h3[os];
        }
    }
}

// ---------------- K5: horizontal box of a,b --------------------------------
__global__ void k_hbox2(const int* __restrict__ rp)
{
    int r = get_r(rp);
    int Wp = Wn + 2*r;
    int row = blockIdx.x;
    int b = row >> 9, y = row & 511;
    int base = (b << 18) + (y << 9);
    int tid = threadIdx.x;

    __shared__ float2 v[MAXWP];
    for (int i = tid; i < Wp; i += blockDim.x) {
        int j = reflW(i - r);
        v[i] = make_float2(g_a[base + j], g_b[base + j]);
    }
    __syncthreads();
    for (int d = 1; d < Wp; d <<= 1) {
        float2 add;
        bool act = (tid < Wp) && (tid >= d);
        if (act) add = v[tid - d];
        __syncthreads();
        if (act) {
            float2 c = v[tid];
            v[tid] = make_float2(c.x+add.x, c.y+add.y);
        }
        __syncthreads();
    }
    if (tid < Wn) {
        float2 s1 = v[tid + 2*r];
        float2 s0 = (tid > 0) ? v[tid - 1] : make_float2(0.f,0.f);
        g_h0[base+tid] = s1.x - s0.x;
        g_h1[base+tid] = s1.y - s0.y;
    }
}

// ---------------- K6: vertical box of a,b + t_final + J --------------------
__global__ void k_vbox_fin(const int* __restrict__ rp,
                           const float* __restrict__ img,
                           const float* __restrict__ atm)
{
    int r = get_r(rp);
    float invk2 = 1.0f / (float)((2*r+1)*(2*r+1));
    int t = blockIdx.x * blockDim.x + threadIdx.x;
    if (t >= Bn * Wn * 8) return;
    int x   = t & 511;
    int seg = (t >> 9) & 7;
    int b   = t >> 12;
    int base = b << 18;
    int y0 = seg << 6;
    float A0 = atm[b*3+0], A1 = atm[b*3+1], A2 = atm[b*3+2];
    const float* ib = img + (size_t)b * 3 * HWn;

    float sa = 0.f, sb = 0.f;
    for (int d = -r; d <= r; d++) {
        int j = reflH(y0 + d);
        int o = base + (j << 9) + x;
        sa += g_h0[o]; sb += g_h1[o];
    }
    for (int yy = 0; yy < 64; yy++) {
        int y = y0 + yy;
        int pix = (y << 9) + x;
        int o = base + pix;
        float ma = sa * invk2, mb = sb * invk2;
        float g = g_gray[o];
        float tf = fminf(fmaxf(ma * g + mb, 0.1f), 1.0f);
        float inv_t = 1.0f / (tf + 1e-8f);
        float i0 = ib[pix], i1 = ib[HWn + pix], i2 = ib[2*HWn + pix];
        float J0 = fminf(fmaxf((i0 - A0) * inv_t + A0, 0.0f), 1.0f);
        float J1 = fminf(fmaxf((i1 - A1) * inv_t + A1, 0.0f), 1.0f);
        float J2 = fminf(fmaxf((i2 - A2) * inv_t + A2, 0.0f), 1.0f);
        g_J[(b*3+0)*HWn + pix] = J0;
        g_J[(b*3+1)*HWn + pix] = J1;
        g_J[(b*3+2)*HWn + pix] = J2;
        if (yy < 63) {
            int ja = reflH(y + 1 + r);
            int js = reflH(y - r);
            sa += g_h0[base + (ja << 9) + x] - g_h0[base + (js << 9) + x];
            sb += g_h1[base + (ja << 9) + x] - g_h1[base + (js << 9) + x];
        }
    }
}

// ---------------- K0: zero histograms (graph replays must reset) -----------
__global__ void k_zero()
{
    int idx = blockIdx.x * blockDim.x + threadIdx.x;
    const int n1 = NBC * NBINS;          // 98304
    const int n2 = NBC * 2 * NBINS;      // 196608
    if (idx < n1) g_hist[idx] = 0u;
    else if (idx < n1 + n2) g_sub[idx - n1] = 0u;
}

// ---------------- K7: coarse histogram (4096 bins, shared-privatized) ------
__global__ void k_hist()
{
    int bc = blockIdx.x >> 2;
    int chunk = blockIdx.x & 3;
    __shared__ unsigned int h[NBINS];
    for (int i = threadIdx.x; i < NBINS; i += blockDim.x) h[i] = 0u;
    __syncthreads();
    int base = bc * HWn + chunk * 65536;
    for (int i = threadIdx.x; i < 65536; i += blockDim.x) {
        float v = g_J[base + i];
        int bin = (int)(v * 4096.0f);
        if (bin > 4095) bin = 4095;
        if (bin < 0) bin = 0;
        atomicAdd(&h[bin], 1u);
    }
    __syncthreads();
    for (int i = threadIdx.x; i < NBINS; i += blockDim.x)
        if (h[i]) atomicAdd(&g_hist[bc * NBINS + i], h[i]);
}

// ---------------- order-statistic bin search helper ------------------------
__device__ void find_kth(const unsigned int* __restrict__ hist,
                         const unsigned int* __restrict__ ps,
                         unsigned int target, int* bin, unsigned int* rank)
{
    unsigned int cum = 0;
    for (int t = 0; t < 128; t++) {
        unsigned int s = ps[t];
        if (cum + s > target) {
            unsigned int c2 = cum;
            for (int i = t*32; ; i++) {
                unsigned int c = hist[i];
                if (c2 + c > target) { *bin = i; *rank = target - c2; return; }
                c2 += c;
            }
        }
        cum += s;
    }
    *bin = NBINS - 1; *rank = 0;
}

// ---------------- K8: coarse select (per (b,c): target bins + ranks) -------
__global__ void k_sel(const float* __restrict__ Ll, const float* __restrict__ Lh)
{
    int bc = blockIdx.x;
    int b = bc / 3;
    const unsigned int* hb = g_hist + bc * NBINS;
    __shared__ unsigned int ps[128];
    unsigned int s = 0;
    for (int i = threadIdx.x * 32; i < threadIdx.x * 32 + 32; i++) s += hb[i];
    ps[threadIdx.x] = s;
    __syncthreads();
    if (threadIdx.x == 0) {
        const int n = HWn;
        float tl = (Ll[b] / 100.0f) * (float)n;
        float th = (Lh[b] / 100.0f) * (float)n;
        int li = (int)tl; if (li < 0) li = 0; if (li > n-1) li = n-1;
        int hi = (int)th; if (hi < 0) hi = 0; if (hi > n-1) hi = n-1;
        int binL, binH; unsigned int rL, rH;
        find_kth(hb, ps, (unsigned int)li, &binL, &rL);
        find_kth(hb, ps, (unsigned int)hi, &binH, &rH);
        g_seld[bc*4+0] = binL; g_seld[bc*4+1] = (int)rL;
        g_seld[bc*4+2] = binH; g_seld[bc*4+3] = (int)rH;
    }
}

// ---------------- K9: sub-histogram refinement -----------------------------
__global__ void k_refine()
{
    int bc = blockIdx.x >> 2;
    int chunk = blockIdx.x & 3;
    int binL = g_seld[bc*4+0];
    int binH = g_seld[bc*4+2];
    __shared__ unsigned int hl[NBINS];
    __shared__ unsigned int hh[NBINS];
    for (int i = threadIdx.x; i < NBINS; i += blockDim.x) { hl[i] = 0u; hh[i] = 0u; }
    __syncthreads();
    int base = bc * HWn + chunk * 65536;
    for (int i = threadIdx.x; i < 65536; i += blockDim.x) {
        float v = g_J[base + i];
        float fb = v * 4096.0f;
        int bin = (int)fb;
        if (bin > 4095) bin = 4095;
        if (bin < 0) bin = 0;
        if (bin == binL) {
            int sub = (int)((fb - (float)binL) * 4096.0f);
            if (sub > 4095) sub = 4095; if (sub < 0) sub = 0;
            atomicAdd(&hl[sub], 1u);
        }
        if (bin == binH) {
            int sub = (int)((fb - (float)binH) * 4096.0f);
            if (sub > 4095) sub = 4095; if (sub < 0) sub = 0;
            atomicAdd(&hh[sub], 1u);
        }
    }
    __syncthreads();
    for (int i = threadIdx.x; i < NBINS; i += blockDim.x) {
        if (hl[i]) atomicAdd(&g_sub[bc*2*NBINS + i], hl[i]);
        if (hh[i]) atomicAdd(&g_sub[bc*2*NBINS + NBINS + i], hh[i]);
    }
}

// ---------------- K10: final percentile values -----------------------------
__global__ void k_sel2()
{
    int bc = blockIdx.x;
    const unsigned int* hl = g_sub + bc * 2 * NBINS;
    const unsigned int* hh = hl + NBINS;
    __shared__ unsigned int psL[128];
    __shared__ unsigned int psH[128];
    unsigned int sL = 0, sH = 0;
    for (int i = threadIdx.x * 32; i < threadIdx.x * 32 + 32; i++) { sL += hl[i]; sH += hh[i]; }
    psL[threadIdx.x] = sL; psH[threadIdx.x] = sH;
    __syncthreads();
    if (threadIdx.x == 0) {
        int binL = g_seld[bc*4+0]; unsigned int rL = (unsigned int)g_seld[bc*4+1];
        int binH = g_seld[bc*4+2]; unsigned int rH = (unsigned int)g_seld[bc*4+3];
        int subL, subH; unsigned int d;
        find_kth(hl, psL, rL, &subL, &d);
        find_kth(hh, psH, rH, &subH, &d);
        const float inv = 1.0f / 4096.0f;
        g_p[bc*2+0] = ((float)binL + (float)subL * inv) * inv;
        g_p[bc*2+1] = ((float)binH + (float)subH * inv) * inv;
    }
}

// ---------------- K11: final stretch (pointwise) ---------------------------
__global__ void k_final(float* __restrict__ out)
{
    int idx = blockIdx.x * blockDim.x + threadIdx.x;
    if (idx >= 3*NPIX) return;
    int bc = idx >> 18;
    float pl = g_p[bc*2+0];
    float ph = g_p[bc*2+1];
    float v = g_J[idx];
    float w = fminf(fmaxf(v, pl), ph);
    float o = (w - pl) / (ph - pl + 1e-8f);
    out[idx] = fminf(fmaxf(o, 0.0f), 1.0f);
}

// ---------------- launch ----------------------------------------------------
extern "C" void kernel_launch(void* const* d_in, const int* in_sizes, int n_in,
                              void* d_out, int out_size)
{
    const float* img   = (const float*)d_in[0];
    const float* omega = (const float*)d_in[1];
    const float* atm   = (const float*)d_in[2];
    const float* Ll    = (const float*)d_in[3];
    const float* Lh    = (const float*)d_in[4];
    const int*   rp    = (const int*)  d_in[5];
    float* out = (float*)d_out;

    k_t0gray<<<NPIX/256, 256>>>(img, omega, atm);
    k_tg<<<NPIX/256, 256>>>();
    k_hbox4<<<Bn*Hn, 640>>>(rp);
    k_vbox_ab<<<(Bn*Wn*8)/256, 256>>>(rp);
    k_hbox2<<<Bn*Hn, 640>>>(rp);
    k_vbox_fin<<<(Bn*Wn*8)/256, 256>>>(rp, img, atm);
    k_zero<<<(NBC*NBINS*3 + 255)/256, 256>>>();
    k_hist<<<NBC*4, 512>>>();
    k_sel<<<NBC, 128>>>(Ll, Lh);
    k_refine<<<NBC*4, 512>>>();
    k_sel2<<<NBC, 128>>>();
    k_final<<<(3*NPIX)/256, 256>>>(out);
}

// round 4
// speedup vs baseline: 1.3371x; 1.3371x over previous
#include <cuda_runtime.h>

#define Bn   8
#define Hn   512
#define Wn   512
#define HWn  (Hn*Wn)        // 262144
#define NPIX (Bn*HWn)       // 2097152
#define NBC  24             // B*3 (b,c) pairs
#define NBINS 4096
#define RMAX 50
#define MAXWP (Wn + 2*RMAX) // 612
#define SEG  16             // rows per thread in vertical passes
#define NSEG (Hn/SEG)       // 32

// ---------------- scratch (no allocation allowed: __device__ globals) -------
__device__ float g_gray[NPIX];
__device__ float g_tg[NPIX];
__device__ float g_h0[NPIX];
__device__ float g_h1[NPIX];
__device__ float g_h2[NPIX];
__device__ float g_h3[NPIX];
__device__ float g_a[NPIX];
__device__ float g_b[NPIX];
__device__ float g_J[3*NPIX];
__device__ unsigned int g_hist[NBC*NBINS];
__device__ unsigned int g_sub[NBC*2*NBINS];
__device__ int   g_seld[NBC*4];   // binL, rankL, binH, rankH
__device__ float g_p[NBC*2];      // p_low, p_high per (b,c)

__device__ __forceinline__ int reflW(int j){ j = j < 0 ? -j : j; return j >= Wn ? 2*Wn - 2 - j : j; }
__device__ __forceinline__ int reflH(int j){ j = j < 0 ? -j : j; return j >= Hn ? 2*Hn - 2 - j : j; }
__device__ __forceinline__ int get_r(const int* rp){ int r = rp[0]; if (r < 1) r = 1; if (r > RMAX) r = RMAX; return r; }

// ---------------- K1: fused t0 -> tg + gray (pointwise, t0 recomputed) -----
__device__ __forceinline__ float t0_at(const float* __restrict__ ib, int pix,
                                       float ra0, float ra1, float ra2, float om)
{
    float i0 = ib[pix], i1 = ib[HWn + pix], i2 = ib[2*HWn + pix];
    float d = fminf(i0 * ra0, fminf(i1 * ra1, i2 * ra2));
    return 1.0f - om * d;
}

__global__ void k_pre(const float* __restrict__ img,
                      const float* __restrict__ omega,
                      const float* __restrict__ atm)
{
    int idx = blockIdx.x * blockDim.x + threadIdx.x;
    if (idx >= NPIX) return;
    int b = idx >> 18;
    int pix = idx & (HWn - 1);
    int y = pix >> 9, x = pix & 511;
    const float* ib = img + (size_t)b * 3 * HWn;
    float om  = omega[b];
    float ra0 = 1.0f / (atm[b*3+0] + 1e-8f);
    float ra1 = 1.0f / (atm[b*3+1] + 1e-8f);
    float ra2 = 1.0f / (atm[b*3+2] + 1e-8f);

    int yy = (y > 0) ? (y - 1) : 0;
    float t_yy_x = t0_at(ib, (yy << 9) + x, ra0, ra1, ra2, om);
    float txv;
    if (x == 0) {
        txv = t_yy_x;
    } else {
        float t_yy_xm1 = t0_at(ib, (yy << 9) + x - 1, ra0, ra1, ra2, om);
        txv = t_yy_xm1 * __expf(-fabsf(t_yy_x - t_yy_xm1));
    }
    float tgv;
    if (y == 0) {
        tgv = txv;
    } else {
        float t_y_x = t0_at(ib, (y << 9) + x, ra0, ra1, ra2, om);
        tgv = txv * __expf(-fabsf(t_y_x - t_yy_x));
    }
    g_tg[idx] = tgv;

    float i0 = ib[pix], i1 = ib[HWn + pix], i2 = ib[2*HWn + pix];
    g_gray[idx] = 0.299f*i0 + 0.587f*i1 + 0.114f*i2;
}

// ---------------- warp shuffle scans ---------------------------------------
__device__ __forceinline__ float4 wscan4(float4 x, int lane)
{
    #pragma unroll
    for (int d = 1; d < 32; d <<= 1) {
        float a = __shfl_up_sync(0xFFFFFFFFu, x.x, d);
        float b = __shfl_up_sync(0xFFFFFFFFu, x.y, d);
        float c = __shfl_up_sync(0xFFFFFFFFu, x.z, d);
        float e = __shfl_up_sync(0xFFFFFFFFu, x.w, d);
        if (lane >= d) { x.x += a; x.y += b; x.z += c; x.w += e; }
    }
    return x;
}
__device__ __forceinline__ float2 wscan2(float2 x, int lane)
{
    #pragma unroll
    for (int d = 1; d < 32; d <<= 1) {
        float a = __shfl_up_sync(0xFFFFFFFFu, x.x, d);
        float b = __shfl_up_sync(0xFFFFFFFFu, x.y, d);
        if (lane >= d) { x.x += a; x.y += b; }
    }
    return x;
}

// ---------------- K2: horizontal box (4 fields, 3-barrier warp scan) -------
__global__ void k_hbox4(const int* __restrict__ rp)
{
    int r = get_r(rp);
    int Wp = Wn + 2*r;
    int row = blockIdx.x;
    int b = row >> 9, y = row & 511;
    int base = (b << 18) + (y << 9);
    int tid = threadIdx.x;
    int lane = tid & 31, wp = tid >> 5;

    __shared__ float4 P[MAXWP];
    __shared__ float4 wsum[20];

    float4 v = make_float4(0.f, 0.f, 0.f, 0.f);
    if (tid < Wp) {
        int j = reflW(tid - r);
        float g = g_gray[base + j];
        float t = g_tg[base + j];
        v = make_float4(g, t, g*t, g*g);
    }
    float4 s = wscan4(v, lane);
    if (lane == 31) wsum[wp] = s;
    __syncthreads();
    if (wp == 0) {
        float4 w = (lane < 20) ? wsum[lane] : make_float4(0.f,0.f,0.f,0.f);
        w = wscan4(w, lane);
        if (lane < 20) wsum[lane] = w;
    }
    __syncthreads();
    if (tid < Wp) {
        float4 off = (wp > 0) ? wsum[wp-1] : make_float4(0.f,0.f,0.f,0.f);
        P[tid] = make_float4(s.x+off.x, s.y+off.y, s.z+off.z, s.w+off.w);
    }
    __syncthreads();
    if (tid < Wn) {
        float4 s1 = P[tid + 2*r];
        float4 s0 = (tid > 0) ? P[tid - 1] : make_float4(0.f,0.f,0.f,0.f);
        g_h0[base+tid] = s1.x - s0.x;
        g_h1[base+tid] = s1.y - s0.y;
        g_h2[base+tid] = s1.z - s0.z;
        g_h3[base+tid] = s1.w - s0.w;
    }
}

// ---------------- K3: vertical box (4 fields) + a,b  (16-row segments) -----
__global__ void k_vbox_ab(const int* __restrict__ rp)
{
    int r = get_r(rp);
    float invk2 = 1.0f / (float)((2*r+1)*(2*r+1));
    int t = blockIdx.x * blockDim.x + threadIdx.x;
    if (t >= Bn * Wn * NSEG) return;
    int x   = t & 511;
    int seg = (t >> 9) & (NSEG - 1);
    int b   = t >> 14;
    int base = b << 18;
    int y0 = seg * SEG;

    float s0 = 0.f, s1 = 0.f, s2 = 0.f, s3 = 0.f;
    for (int d = -r; d <= r; d++) {
        int j = reflH(y0 + d);
        int o = base + (j << 9) + x;
        s0 += g_h0[o]; s1 += g_h1[o]; s2 += g_h2[o]; s3 += g_h3[o];
    }
    #pragma unroll 4
    for (int yy = 0; yy < SEG; yy++) {
        int y = y0 + yy;
        int o = base + (y << 9) + x;
        float mI  = s0 * invk2, mp = s1 * invk2;
        float mIp = s2 * invk2, mII = s3 * invk2;
        float a  = (mIp - mI*mp) / (mII - mI*mI + 0.5f);
        float bb = mp - a * mI;
        g_a[o] = a;
        g_b[o] = bb;
        if (yy < SEG - 1) {
            int ja = reflH(y + 1 + r);
            int js = reflH(y - r);
            int oa = base + (ja << 9) + x;
            int os = base + (js << 9) + x;
            s0 += g_h0[oa] - g_h0[os];
            s1 += g_h1[oa] - g_h1[os];
            s2 += g_h2[oa] - g_h2[os];
            s3 += g_h3[oa] - g_h3[os];
        }
    }
}

// ---------------- K4: horizontal box of a,b --------------------------------
__global__ void k_hbox2(const int* __restrict__ rp)
{
    int r = get_r(rp);
    int Wp = Wn + 2*r;
    int row = blockIdx.x;
    int b = row >> 9, y = row & 511;
    int base = (b << 18) + (y << 9);
    int tid = threadIdx.x;
    int lane = tid & 31, wp = tid >> 5;

    __shared__ float2 P[MAXWP];
    __shared__ float2 wsum[20];

    float2 v = make_float2(0.f, 0.f);
    if (tid < Wp) {
        int j = reflW(tid - r);
        v = make_float2(g_a[base + j], g_b[base + j]);
    }
    float2 s = wscan2(v, lane);
    if (lane == 31) wsum[wp] = s;
    __syncthreads();
    if (wp == 0) {
        float2 w = (lane < 20) ? wsum[lane] : make_float2(0.f,0.f);
        w = wscan2(w, lane);
        if (lane < 20) wsum[lane] = w;
    }
    __syncthreads();
    if (tid < Wp) {
        float2 off = (wp > 0) ? wsum[wp-1] : make_float2(0.f,0.f);
        P[tid] = make_float2(s.x+off.x, s.y+off.y);
    }
    __syncthreads();
    if (tid < Wn) {
        float2 s1 = P[tid + 2*r];
        float2 s0 = (tid > 0) ? P[tid - 1] : make_float2(0.f,0.f);
        g_h0[base+tid] = s1.x - s0.x;
        g_h1[base+tid] = s1.y - s0.y;
    }
}

// ---------------- K5: vertical box of a,b + t_final + J (16-row segments) --
__global__ void k_vbox_fin(const int* __restrict__ rp,
                           const float* __restrict__ img,
                           const float* __restrict__ atm)
{
    int r = get_r(rp);
    float invk2 = 1.0f / (float)((2*r+1)*(2*r+1));
    int t = blockIdx.x * blockDim.x + threadIdx.x;
    if (t >= Bn * Wn * NSEG) return;
    int x   = t & 511;
    int seg = (t >> 9) & (NSEG - 1);
    int b   = t >> 14;
    int base = b << 18;
    int y0 = seg * SEG;
    float A0 = atm[b*3+0], A1 = atm[b*3+1], A2 = atm[b*3+2];
    const float* ib = img + (size_t)b * 3 * HWn;

    float sa = 0.f, sb = 0.f;
    for (int d = -r; d <= r; d++) {
        int j = reflH(y0 + d);
        int o = base + (j << 9) + x;
        sa += g_h0[o]; sb += g_h1[o];
    }
    #pragma unroll 4
    for (int yy = 0; yy < SEG; yy++) {
        int y = y0 + yy;
        int pix = (y << 9) + x;
        int o = base + pix;
        float ma = sa * invk2, mb = sb * invk2;
        float g = g_gray[o];
        float tf = fminf(fmaxf(ma * g + mb, 0.1f), 1.0f);
        float inv_t = 1.0f / (tf + 1e-8f);
        float i0 = ib[pix], i1 = ib[HWn + pix], i2 = ib[2*HWn + pix];
        float J0 = fminf(fmaxf((i0 - A0) * inv_t + A0, 0.0f), 1.0f);
        float J1 = fminf(fmaxf((i1 - A1) * inv_t + A1, 0.0f), 1.0f);
        float J2 = fminf(fmaxf((i2 - A2) * inv_t + A2, 0.0f), 1.0f);
        g_J[(b*3+0)*HWn + pix] = J0;
        g_J[(b*3+1)*HWn + pix] = J1;
        g_J[(b*3+2)*HWn + pix] = J2;
        if (yy < SEG - 1) {
            int ja = reflH(y + 1 + r);
            int js = reflH(y - r);
            sa += g_h0[base + (ja << 9) + x] - g_h0[base + (js << 9) + x];
            sb += g_h1[base + (ja << 9) + x] - g_h1[base + (js << 9) + x];
        }
    }
}

// ---------------- K0: zero histograms (graph replays must reset) -----------
__global__ void k_zero()
{
    int idx = blockIdx.x * blockDim.x + threadIdx.x;
    const int n1 = NBC * NBINS;          // 98304
    const int n2 = NBC * 2 * NBINS;      // 196608
    if (idx < n1) g_hist[idx] = 0u;
    else if (idx < n1 + n2) g_sub[idx - n1] = 0u;
}

// ---------------- K6: coarse histogram (4096 bins, shared-privatized) ------
__global__ void k_hist()
{
    int bc = blockIdx.x >> 2;
    int chunk = blockIdx.x & 3;
    __shared__ unsigned int h[NBINS];
    for (int i = threadIdx.x; i < NBINS; i += blockDim.x) h[i] = 0u;
    __syncthreads();
    const float4* J4 = reinterpret_cast<const float4*>(g_J);
    int base4 = bc * (HWn/4) + chunk * 16384;
    for (int i = threadIdx.x; i < 16384; i += blockDim.x) {
        float4 v = J4[base4 + i];
        int b0 = min(max((int)(v.x * 4096.0f), 0), 4095);
        int b1 = min(max((int)(v.y * 4096.0f), 0), 4095);
        int b2 = min(max((int)(v.z * 4096.0f), 0), 4095);
        int b3 = min(max((int)(v.w * 4096.0f), 0), 4095);
        atomicAdd(&h[b0], 1u);
        atomicAdd(&h[b1], 1u);
        atomicAdd(&h[b2], 1u);
        atomicAdd(&h[b3], 1u);
    }
    __syncthreads();
    for (int i = threadIdx.x; i < NBINS; i += blockDim.x)
        if (h[i]) atomicAdd(&g_hist[bc * NBINS + i], h[i]);
}

// ---------------- order-statistic bin search helper ------------------------
__device__ void find_kth(const unsigned int* __restrict__ hist,
                         const unsigned int* __restrict__ ps,
                         unsigned int target, int* bin, unsigned int* rank)
{
    unsigned int cum = 0;
    for (int t = 0; t < 128; t++) {
        unsigned int s = ps[t];
        if (cum + s > target) {
            unsigned int c2 = cum;
            for (int i = t*32; ; i++) {
                unsigned int c = hist[i];
                if (c2 + c > target) { *bin = i; *rank = target - c2; return; }
                c2 += c;
            }
        }
        cum += s;
    }
    *bin = NBINS - 1; *rank = 0;
}

// ---------------- K7: coarse select (per (b,c): target bins + ranks) -------
__global__ void k_sel(const float* __restrict__ Ll, const float* __restrict__ Lh)
{
    int bc = blockIdx.x;
    int b = bc / 3;
    const unsigned int* hb = g_hist + bc * NBINS;
    __shared__ unsigned int ps[128];
    unsigned int s = 0;
    for (int i = threadIdx.x * 32; i < threadIdx.x * 32 + 32; i++) s += hb[i];
    ps[threadIdx.x] = s;
    __syncthreads();
    if (threadIdx.x == 0) {
        const int n = HWn;
        float tl = (Ll[b] / 100.0f) * (float)n;
        float th = (Lh[b] / 100.0f) * (float)n;
        int li = (int)tl; if (li < 0) li = 0; if (li > n-1) li = n-1;
        int hi = (int)th; if (hi < 0) hi = 0; if (hi > n-1) hi = n-1;
        int binL, binH; unsigned int rL, rH;
        find_kth(hb, ps, (unsigned int)li, &binL, &rL);
        find_kth(hb, ps, (unsigned int)hi, &binH, &rH);
        g_seld[bc*4+0] = binL; g_seld[bc*4+1] = (int)rL;
        g_seld[bc*4+2] = binH; g_seld[bc*4+3] = (int)rH;
    }
}

// ---------------- K8: sub-histogram refinement -----------------------------
__global__ void k_refine()
{
    int bc = blockIdx.x >> 2;
    int chunk = blockIdx.x & 3;
    int binL = g_seld[bc*4+0];
    int binH = g_seld[bc*4+2];
    __shared__ unsigned int hl[NBINS];
    __shared__ unsigned int hh[NBINS];
    for (int i = threadIdx.x; i < NBINS; i += blockDim.x) { hl[i] = 0u; hh[i] = 0u; }
    __syncthreads();
    const float4* J4 = reinterpret_cast<const float4*>(g_J);
    int base4 = bc * (HWn/4) + chunk * 16384;
    for (int i = threadIdx.x; i < 16384; i += blockDim.x) {
        float4 v4 = J4[base4 + i];
        float vv[4] = {v4.x, v4.y, v4.z, v4.w};
        #pragma unroll
        for (int q = 0; q < 4; q++) {
            float fb = vv[q] * 4096.0f;
            int bin = min(max((int)fb, 0), 4095);
            if (bin == binL) {
                int sub = min(max((int)((fb - (float)binL) * 4096.0f), 0), 4095);
                atomicAdd(&hl[sub], 1u);
            }
            if (bin == binH) {
                int sub = min(max((int)((fb - (float)binH) * 4096.0f), 0), 4095);
                atomicAdd(&hh[sub], 1u);
            }
        }
    }
    __syncthreads();
    for (int i = threadIdx.x; i < NBINS; i += blockDim.x) {
        if (hl[i]) atomicAdd(&g_sub[bc*2*NBINS + i], hl[i]);
        if (hh[i]) atomicAdd(&g_sub[bc*2*NBINS + NBINS + i], hh[i]);
    }
}

// ---------------- K9: final percentile values ------------------------------
__global__ void k_sel2()
{
    int bc = blockIdx.x;
    const unsigned int* hl = g_sub + bc * 2 * NBINS;
    const unsigned int* hh = hl + NBINS;
    __shared__ unsigned int psL[128];
    __shared__ unsigned int psH[128];
    unsigned int sL = 0, sH = 0;
    for (int i = threadIdx.x * 32; i < threadIdx.x * 32 + 32; i++) { sL += hl[i]; sH += hh[i]; }
    psL[threadIdx.x] = sL; psH[threadIdx.x] = sH;
    __syncthreads();
    if (threadIdx.x == 0) {
        int binL = g_seld[bc*4+0]; unsigned int rL = (unsigned int)g_seld[bc*4+1];
        int binH = g_seld[bc*4+2]; unsigned int rH = (unsigned int)g_seld[bc*4+3];
        int subL, subH; unsigned int d;
        find_kth(hl, psL, rL, &subL, &d);
        find_kth(hh, psH, rH, &subH, &d);
        const float inv = 1.0f / 4096.0f;
        g_p[bc*2+0] = ((float)binL + (float)subL * inv) * inv;
        g_p[bc*2+1] = ((float)binH + (float)subH * inv) * inv;
    }
}

// ---------------- K10: final stretch (pointwise, float4) -------------------
__global__ void k_final(float4* __restrict__ out)
{
    int idx = blockIdx.x * blockDim.x + threadIdx.x;
    if (idx >= 3*NPIX/4) return;
    int bc = idx >> 16;                    // HWn/4 = 65536 float4 per (b,c)
    float pl = g_p[bc*2+0];
    float ph = g_p[bc*2+1];
    float inv = 1.0f / (ph - pl + 1e-8f);
    const float4* J4 = reinterpret_cast<const float4*>(g_J);
    float4 v = J4[idx];
    float4 o;
    o.x = fminf(fmaxf((fminf(fmaxf(v.x, pl), ph) - pl) * inv, 0.0f), 1.0f);
    o.y = fminf(fmaxf((fminf(fmaxf(v.y, pl), ph) - pl) * inv, 0.0f), 1.0f);
    o.z = fminf(fmaxf((fminf(fmaxf(v.z, pl), ph) - pl) * inv, 0.0f), 1.0f);
    o.w = fminf(fmaxf((fminf(fmaxf(v.w, pl), ph) - pl) * inv, 0.0f), 1.0f);
    out[idx] = o;
}

// ---------------- launch ----------------------------------------------------
extern "C" void kernel_launch(void* const* d_in, const int* in_sizes, int n_in,
                              void* d_out, int out_size)
{
    const float* img   = (const float*)d_in[0];
    const float* omega = (const float*)d_in[1];
    const float* atm   = (const float*)d_in[2];
    const float* Ll    = (const float*)d_in[3];
    const float* Lh    = (const float*)d_in[4];
    const int*   rp    = (const int*)  d_in[5];
    float4* out = (float4*)d_out;

    k_pre<<<NPIX/256, 256>>>(img, omega, atm);
    k_hbox4<<<Bn*Hn, 640>>>(rp);
    k_vbox_ab<<<(Bn*Wn*NSEG)/256, 256>>>(rp);
    k_hbox2<<<Bn*Hn, 640>>>(rp);
    k_vbox_fin<<<(Bn*Wn*NSEG)/256, 256>>>(rp, img, atm);
    k_zero<<<(NBC*NBINS*3 + 255)/256, 256>>>();
    k_hist<<<NBC*4, 512>>>();
    k_sel<<<NBC, 128>>>(Ll, Lh);
    k_refine<<<NBC*4, 512>>>();
    k_sel2<<<NBC, 128>>>();
    k_final<<<(3*NPIX/4 + 255)/256, 256>>>(out);
}

// round 6
// speedup vs baseline: 2.3220x; 1.7366x over previous
#include <cuda_runtime.h>

#define Bn   8
#define Hn   512
#define Wn   512
#define HWn  (Hn*Wn)        // 262144
#define NPIX (Bn*HWn)       // 2097152
#define NBC  24             // B*3 (b,c) pairs
#define NBINS 4096
#define RMAX 50
#define MAXWP (Wn + 2*RMAX) // 612
#define SEG  8              // rows per thread in vertical passes
#define NSEG (Hn/SEG)       // 64
#define HB_T 160            // hbox threads (160*4 = 640 >= MAXWP)

// ---------------- scratch (no allocation allowed: __device__ globals) -------
__device__ float g_h0[NPIX];
__device__ float g_h1[NPIX];
__device__ float g_h2[NPIX];
__device__ float g_h3[NPIX];
__device__ float g_a[NPIX];
__device__ float g_b[NPIX];
__device__ float g_J[3*NPIX];
__device__ unsigned int g_hist[NBC*NBINS];
__device__ unsigned int g_sub[NBC*2*NBINS];
__device__ int   g_seld[NBC*4];   // binL, rankL, binH, rankH
__device__ float g_p[NBC*2];      // p_low, p_high per (b,c)

__device__ __forceinline__ int reflW(int j){ j = j < 0 ? -j : j; return j >= Wn ? 2*Wn - 2 - j : j; }
__device__ __forceinline__ int reflH(int j){ j = j < 0 ? -j : j; return j >= Hn ? 2*Hn - 2 - j : j; }
__device__ __forceinline__ int get_r(const int* rp){ int r = rp[0]; if (r < 1) r = 1; if (r > RMAX) r = RMAX; return r; }

__device__ __forceinline__ float4 f4add(float4 a, float4 b){ return make_float4(a.x+b.x,a.y+b.y,a.z+b.z,a.w+b.w); }
__device__ __forceinline__ float4 f4sub(float4 a, float4 b){ return make_float4(a.x-b.x,a.y-b.y,a.z-b.z,a.w-b.w); }
__device__ __forceinline__ float2 f2add(float2 a, float2 b){ return make_float2(a.x+b.x,a.y+b.y); }
__device__ __forceinline__ float2 f2sub(float2 a, float2 b){ return make_float2(a.x-b.x,a.y-b.y); }

__device__ __forceinline__ float t0_at(const float* __restrict__ ib, int pix,
                                       float ra0, float ra1, float ra2, float om)
{
    float i0 = ib[pix], i1 = ib[HWn + pix], i2 = ib[2*HWn + pix];
    float d = fminf(i0 * ra0, fminf(i1 * ra1, i2 * ra2));
    return 1.0f - om * d;
}

// ---------------- warp shuffle scans ---------------------------------------
__device__ __forceinline__ float4 wscan4(float4 x, int lane)
{
    #pragma unroll
    for (int d = 1; d < 32; d <<= 1) {
        float a = __shfl_up_sync(0xFFFFFFFFu, x.x, d);
        float b = __shfl_up_sync(0xFFFFFFFFu, x.y, d);
        float c = __shfl_up_sync(0xFFFFFFFFu, x.z, d);
        float e = __shfl_up_sync(0xFFFFFFFFu, x.w, d);
        if (lane >= d) { x.x += a; x.y += b; x.z += c; x.w += e; }
    }
    return x;
}
__device__ __forceinline__ float2 wscan2(float2 x, int lane)
{
    #pragma unroll
    for (int d = 1; d < 32; d <<= 1) {
        float a = __shfl_up_sync(0xFFFFFFFFu, x.x, d);
        float b = __shfl_up_sync(0xFFFFFFFFu, x.y, d);
        if (lane >= d) { x.x += a; x.y += b; }
    }
    return x;
}

// ---------------- K1: fused gray/tg + horizontal box (4 elems/thread) ------
__global__ void k_hbox4(const int* __restrict__ rp,
                        const float* __restrict__ img,
                        const float* __restrict__ omega,
                        const float* __restrict__ atm)
{
    int r = get_r(rp);
    int Wp = Wn + 2*r;
    int row = blockIdx.x;
    int b = row >> 9, y = row & 511;
    int base = (b << 18) + (y << 9);
    const float* ib = img + (size_t)b * 3 * HWn;
    float om  = omega[b];
    float ra0 = 1.0f / (atm[b*3+0] + 1e-8f);
    float ra1 = 1.0f / (atm[b*3+1] + 1e-8f);
    float ra2 = 1.0f / (atm[b*3+2] + 1e-8f);
    int tid = threadIdx.x;
    int lane = tid & 31, wp = tid >> 5;

    __shared__ float4 P[MAXWP];
    __shared__ float4 wtot[HB_T/32];

    int yy = (y > 0) ? (y - 1) : 0;
    float4 loc[4];
    float4 run = make_float4(0.f,0.f,0.f,0.f);
    #pragma unroll
    for (int q = 0; q < 4; q++) {
        int i = tid * 4 + q;
        float4 v = make_float4(0.f,0.f,0.f,0.f);
        if (i < Wp) {
            int j = reflW(i - r);
            int pix = (y << 9) + j;
            float i0 = ib[pix], i1 = ib[HWn + pix], i2 = ib[2*HWn + pix];
            float g = 0.299f*i0 + 0.587f*i1 + 0.114f*i2;
            // tg recompute from img
            float t_yy_x = t0_at(ib, (yy << 9) + j, ra0, ra1, ra2, om);
            float txv;
            if (j == 0) {
                txv = t_yy_x;
            } else {
                float tm = t0_at(ib, (yy << 9) + j - 1, ra0, ra1, ra2, om);
                txv = tm * __expf(-fabsf(t_yy_x - tm));
            }
            float tg;
            if (y == 0) {
                tg = txv;
            } else {
                float tc = t0_at(ib, pix, ra0, ra1, ra2, om);
                tg = txv * __expf(-fabsf(tc - t_yy_x));
            }
            v = make_float4(g, tg, g*tg, g*g);
        }
        run = f4add(run, v);
        loc[q] = run;
    }
    float4 tot = run;
    float4 sc = wscan4(tot, lane);            // inclusive across threads in warp
    float4 excl = f4sub(sc, tot);
    if (lane == 31) wtot[wp] = sc;
    __syncthreads();
    float4 woff = make_float4(0.f,0.f,0.f,0.f);
    #pragma unroll
    for (int w = 0; w < HB_T/32; w++)
        if (w < wp) woff = f4add(woff, wtot[w]);
    float4 off = f4add(excl, woff);
    #pragma unroll
    for (int q = 0; q < 4; q++) {
        int i = tid * 4 + q;
        if (i < Wp) P[i] = f4add(loc[q], off);
    }
    __syncthreads();
    for (int t = tid; t < Wn; t += HB_T) {
        float4 s1 = P[t + 2*r];
        float4 s0 = (t > 0) ? P[t - 1] : make_float4(0.f,0.f,0.f,0.f);
        g_h0[base+t] = s1.x - s0.x;
        g_h1[base+t] = s1.y - s0.y;
        g_h2[base+t] = s1.z - s0.z;
        g_h3[base+t] = s1.w - s0.w;
    }
}

// ---------------- K2: vertical box (4 fields) + a,b  (8-row segments) ------
__global__ void k_vbox_ab(const int* __restrict__ rp)
{
    int r = get_r(rp);
    float invk2 = 1.0f / (float)((2*r+1)*(2*r+1));
    int t = blockIdx.x * blockDim.x + threadIdx.x;
    if (t >= Bn * Wn * NSEG) return;
    int x   = t & 511;
    int seg = (t >> 9) & (NSEG - 1);
    int b   = t >> 15;
    int base = b << 18;
    int y0 = seg * SEG;

    float s0 = 0.f, s1 = 0.f, s2 = 0.f, s3 = 0.f;
    for (int d = -r; d <= r; d++) {
        int j = reflH(y0 + d);
        int o = base + (j << 9) + x;
        s0 += g_h0[o]; s1 += g_h1[o]; s2 += g_h2[o]; s3 += g_h3[o];
    }
    #pragma unroll
    for (int yy = 0; yy < SEG; yy++) {
        int y = y0 + yy;
        int o = base + (y << 9) + x;
        float mI  = s0 * invk2, mp = s1 * invk2;
        float mIp = s2 * invk2, mII = s3 * invk2;
        float a  = (mIp - mI*mp) / (mII - mI*mI + 0.5f);
        float bb = mp - a * mI;
        g_a[o] = a;
        g_b[o] = bb;
        if (yy < SEG - 1) {
            int ja = reflH(y + 1 + r);
            int js = reflH(y - r);
            int oa = base + (ja << 9) + x;
            int os = base + (js << 9) + x;
            s0 += g_h0[oa] - g_h0[os];
            s1 += g_h1[oa] - g_h1[os];
            s2 += g_h2[oa] - g_h2[os];
            s3 += g_h3[oa] - g_h3[os];
        }
    }
}

// ---------------- K3: horizontal box of a,b (4 elems/thread) ---------------
__global__ void k_hbox2(const int* __restrict__ rp)
{
    int r = get_r(rp);
    int Wp = Wn + 2*r;
    int row = blockIdx.x;
    int b = row >> 9, y = row & 511;
    int base = (b << 18) + (y << 9);
    int tid = threadIdx.x;
    int lane = tid & 31, wp = tid >> 5;

    __shared__ float2 P[MAXWP];
    __shared__ float2 wtot[HB_T/32];

    float2 loc[4];
    float2 run = make_float2(0.f,0.f);
    #pragma unroll
    for (int q = 0; q < 4; q++) {
        int i = tid * 4 + q;
        float2 v = make_float2(0.f,0.f);
        if (i < Wp) {
            int j = reflW(i - r);
            v = make_float2(g_a[base + j], g_b[base + j]);
        }
        run = f2add(run, v);
        loc[q] = run;
    }
    float2 tot = run;
    float2 sc = wscan2(tot, lane);
    float2 excl = f2sub(sc, tot);
    if (lane == 31) wtot[wp] = sc;
    __syncthreads();
    float2 woff = make_float2(0.f,0.f);
    #pragma unroll
    for (int w = 0; w < HB_T/32; w++)
        if (w < wp) woff = f2add(woff, wtot[w]);
    float2 off = f2add(excl, woff);
    #pragma unroll
    for (int q = 0; q < 4; q++) {
        int i = tid * 4 + q;
        if (i < Wp) P[i] = f2add(loc[q], off);
    }
    __syncthreads();
    for (int t = tid; t < Wn; t += HB_T) {
        float2 s1 = P[t + 2*r];
        float2 s0 = (t > 0) ? P[t - 1] : make_float2(0.f,0.f);
        g_h0[base+t] = s1.x - s0.x;
        g_h1[base+t] = s1.y - s0.y;
    }
}

// ---------------- K4: vertical box of a,b + t_final + J (8-row segments) ---
__global__ void k_vbox_fin(const int* __restrict__ rp,
                           const float* __restrict__ img,
                           const float* __restrict__ atm)
{
    int r = get_r(rp);
    float invk2 = 1.0f / (float)((2*r+1)*(2*r+1));
    int t = blockIdx.x * blockDim.x + threadIdx.x;
    if (t >= Bn * Wn * NSEG) return;
    int x   = t & 511;
    int seg = (t >> 9) & (NSEG - 1);
    int b   = t >> 15;
    int base = b << 18;
    int y0 = seg * SEG;
    float A0 = atm[b*3+0], A1 = atm[b*3+1], A2 = atm[b*3+2];
    const float* ib = img + (size_t)b * 3 * HWn;

    float sa = 0.f, sb = 0.f;
    for (int d = -r; d <= r; d++) {
        int j = reflH(y0 + d);
        int o = base + (j << 9) + x;
        sa += g_h0[o]; sb += g_h1[o];
    }
    #pragma unroll
    for (int yy = 0; yy < SEG; yy++) {
        int y = y0 + yy;
        int pix = (y << 9) + x;
        float ma = sa * invk2, mb = sb * invk2;
        float i0 = ib[pix], i1 = ib[HWn + pix], i2 = ib[2*HWn + pix];
        float g = 0.299f*i0 + 0.587f*i1 + 0.114f*i2;
        float tf = fminf(fmaxf(ma * g + mb, 0.1f), 1.0f);
        float inv_t = 1.0f / (tf + 1e-8f);
        float J0 = fminf(fmaxf((i0 - A0) * inv_t + A0, 0.0f), 1.0f);
        float J1 = fminf(fmaxf((i1 - A1) * inv_t + A1, 0.0f), 1.0f);
        float J2 = fminf(fmaxf((i2 - A2) * inv_t + A2, 0.0f), 1.0f);
        g_J[(b*3+0)*HWn + pix] = J0;
        g_J[(b*3+1)*HWn + pix] = J1;
        g_J[(b*3+2)*HWn + pix] = J2;
        if (yy < SEG - 1) {
            int ja = reflH(y + 1 + r);
            int js = reflH(y - r);
            sa += g_h0[base + (ja << 9) + x] - g_h0[base + (js << 9) + x];
            sb += g_h1[base + (ja << 9) + x] - g_h1[base + (js << 9) + x];
        }
    }
}

// ---------------- K0: zero histograms (graph replays must reset) -----------
__global__ void k_zero()
{
    int idx = blockIdx.x * blockDim.x + threadIdx.x;
    const int n1 = NBC * NBINS;
    const int n2 = NBC * 2 * NBINS;
    if (idx < n1) g_hist[idx] = 0u;
    else if (idx < n1 + n2) g_sub[idx - n1] = 0u;
}

// ---------------- K5: coarse histogram (16 chunks per bc) ------------------
__global__ void k_hist()
{
    int bc = blockIdx.x >> 4;
    int chunk = blockIdx.x & 15;
    __shared__ unsigned int h[NBINS];
    for (int i = threadIdx.x; i < NBINS; i += blockDim.x) h[i] = 0u;
    __syncthreads();
    const float4* J4 = reinterpret_cast<const float4*>(g_J);
    int base4 = bc * (HWn/4) + chunk * 4096;
    for (int i = threadIdx.x; i < 4096; i += blockDim.x) {
        float4 v = J4[base4 + i];
        int b0 = min(max((int)(v.x * 4096.0f), 0), 4095);
        int b1 = min(max((int)(v.y * 4096.0f), 0), 4095);
        int b2 = min(max((int)(v.z * 4096.0f), 0), 4095);
        int b3 = min(max((int)(v.w * 4096.0f), 0), 4095);
        atomicAdd(&h[b0], 1u);
        atomicAdd(&h[b1], 1u);
        atomicAdd(&h[b2], 1u);
        atomicAdd(&h[b3], 1u);
    }
    __syncthreads();
    for (int i = threadIdx.x; i < NBINS; i += blockDim.x)
        if (h[i]) atomicAdd(&g_hist[bc * NBINS + i], h[i]);
}

// ---------------- order-statistic bin search helper ------------------------
__device__ void find_kth(const unsigned int* __restrict__ hist,
                         const unsigned int* __restrict__ ps,
                         unsigned int target, int* bin, unsigned int* rank)
{
    unsigned int cum = 0;
    for (int t = 0; t < 128; t++) {
        unsigned int s = ps[t];
        if (cum + s > target) {
            unsigned int c2 = cum;
            for (int i = t*32; ; i++) {
                unsigned int c = hist[i];
                if (c2 + c > target) { *bin = i; *rank = target - c2; return; }
                c2 += c;
            }
        }
        cum += s;
    }
    *bin = NBINS - 1; *rank = 0;
}

// ---------------- K6: coarse select ----------------------------------------
__global__ void k_sel(const float* __restrict__ Ll, const float* __restrict__ Lh)
{
    int bc = blockIdx.x;
    int b = bc / 3;
    const unsigned int* hb = g_hist + bc * NBINS;
    __shared__ unsigned int ps[128];
    unsigned int s = 0;
    for (int i = threadIdx.x * 32; i < threadIdx.x * 32 + 32; i++) s += hb[i];
    ps[threadIdx.x] = s;
    __syncthreads();
    if (threadIdx.x == 0) {
        const int n = HWn;
        float tl = (Ll[b] / 100.0f) * (float)n;
        float th = (Lh[b] / 100.0f) * (float)n;
        int li = (int)tl; if (li < 0) li = 0; if (li > n-1) li = n-1;
        int hi = (int)th; if (hi < 0) hi = 0; if (hi > n-1) hi = n-1;
        int binL, binH; unsigned int rL, rH;
        find_kth(hb, ps, (unsigned int)li, &binL, &rL);
        find_kth(hb, ps, (unsigned int)hi, &binH, &rH);
        g_seld[bc*4+0] = binL; g_seld[bc*4+1] = (int)rL;
        g_seld[bc*4+2] = binH; g_seld[bc*4+3] = (int)rH;
    }
}

// ---------------- K7: sub-histogram refinement (16 chunks per bc) ----------
__global__ void k_refine()
{
    int bc = blockIdx.x >> 4;
    int chunk = blockIdx.x & 15;
    int binL = g_seld[bc*4+0];
    int binH = g_seld[bc*4+2];
    __shared__ unsigned int hl[NBINS];
    __shared__ unsigned int hh[NBINS];
    for (int i = threadIdx.x; i < NBINS; i += blockDim.x) { hl[i] = 0u; hh[i] = 0u; }
    __syncthreads();
    const float4* J4 = reinterpret_cast<const float4*>(g_J);
    int base4 = bc * (HWn/4) + chunk * 4096;
    for (int i = threadIdx.x; i < 4096; i += blockDim.x) {
        float4 v4 = J4[base4 + i];
        float vv[4] = {v4.x, v4.y, v4.z, v4.w};
        #pragma unroll
        for (int q = 0; q < 4; q++) {
            float fb = vv[q] * 4096.0f;
            int bin = min(max((int)fb, 0), 4095);
            if (bin == binL) {
                int sub = min(max((int)((fb - (float)binL) * 4096.0f), 0), 4095);
                atomicAdd(&hl[sub], 1u);
            }
            if (bin == binH) {
                int sub = min(max((int)((fb - (float)binH) * 4096.0f), 0), 4095);
                atomicAdd(&hh[sub], 1u);
            }
        }
    }
    __syncthreads();
    for (int i = threadIdx.x; i < NBINS; i += blockDim.x) {
        if (hl[i]) atomicAdd(&g_sub[bc*2*NBINS + i], hl[i]);
        if (hh[i]) atomicAdd(&g_sub[bc*2*NBINS + NBINS + i], hh[i]);
    }
}

// ---------------- K8: final percentile values ------------------------------
__global__ void k_sel2()
{
    int bc = blockIdx.x;
    const unsigned int* hl = g_sub + bc * 2 * NBINS;
    const unsigned int* hh = hl + NBINS;
    __shared__ unsigned int psL[128];
    __shared__ unsigned int psH[128];
    unsigned int sL = 0, sH = 0;
    for (int i = threadIdx.x * 32; i < threadIdx.x * 32 + 32; i++) { sL += hl[i]; sH += hh[i]; }
    psL[threadIdx.x] = sL; psH[threadIdx.x] = sH;
    __syncthreads();
    if (threadIdx.x == 0) {
        int binL = g_seld[bc*4+0]; unsigned int rL = (unsigned int)g_seld[bc*4+1];
        int binH = g_seld[bc*4+2]; unsigned int rH = (unsigned int)g_seld[bc*4+3];
        int subL, subH; unsigned int d;
        find_kth(hl, psL, rL, &subL, &d);
        find_kth(hh, psH, rH, &subH, &d);
        const float inv = 1.0f / 4096.0f;
        g_p[bc*2+0] = ((float)binL + (float)subL * inv) * inv;
        g_p[bc*2+1] = ((float)binH + (float)subH * inv) * inv;
    }
}

// ---------------- K9: final stretch (pointwise, float4) --------------------
__global__ void k_final(float4* __restrict__ out)
{
    int idx = blockIdx.x * blockDim.x + threadIdx.x;
    if (idx >= 3*NPIX/4) return;
    int bc = idx >> 16;
    float pl = g_p[bc*2+0];
    float ph = g_p[bc*2+1];
    float inv = 1.0f / (ph - pl + 1e-8f);
    const float4* J4 = reinterpret_cast<const float4*>(g_J);
    float4 v = J4[idx];
    float4 o;
    o.x = fminf(fmaxf((fminf(fmaxf(v.x, pl), ph) - pl) * inv, 0.0f), 1.0f);
    o.y = fminf(fmaxf((fminf(fmaxf(v.y, pl), ph) - pl) * inv, 0.0f), 1.0f);
    o.z = fminf(fmaxf((fminf(fmaxf(v.z, pl), ph) - pl) * inv, 0.0f), 1.0f);
    o.w = fminf(fmaxf((fminf(fmaxf(v.w, pl), ph) - pl) * inv, 0.0f), 1.0f);
    out[idx] = o;
}

// ---------------- launch ----------------------------------------------------
extern "C" void kernel_launch(void* const* d_in, const int* in_sizes, int n_in,
                              void* d_out, int out_size)
{
    const float* img   = (const float*)d_in[0];
    const float* omega = (const float*)d_in[1];
    const float* atm   = (const float*)d_in[2];
    const float* Ll    = (const float*)d_in[3];
    const float* Lh    = (const float*)d_in[4];
    const int*   rp    = (const int*)  d_in[5];
    float4* out = (float4*)d_out;

    k_hbox4<<<Bn*Hn, HB_T>>>(rp, img, omega, atm);
    k_vbox_ab<<<(Bn*Wn*NSEG)/256, 256>>>(rp);
    k_hbox2<<<Bn*Hn, HB_T>>>(rp);
    k_vbox_fin<<<(Bn*Wn*NSEG)/256, 256>>>(rp, img, atm);
    k_zero<<<(NBC*NBINS*3 + 255)/256, 256>>>();
    k_hist<<<NBC*16, 512>>>();
    k_sel<<<NBC, 128>>>(Ll, Lh);
    k_refine<<<NBC*16, 512>>>();
    k_sel2<<<NBC, 128>>>();
    k_final<<<(3*NPIX/4 + 255)/256, 256>>>(out);
}

// round 7
// speedup vs baseline: 2.8277x; 1.2178x over previous
#include <cuda_runtime.h>

#define Bn   8
#define Hn   512
#define Wn   512
#define HWn  (Hn*Wn)        // 262144
#define NPIX (Bn*HWn)       // 2097152
#define NBC  24             // B*3 (b,c) pairs
#define NBINS 4096
#define RMAX 50
#define MAXWP (Wn + 2*RMAX) // 612
#define SEG  8              // rows per thread in vertical passes
#define NSEG (Hn/SEG)       // 64
#define HB_T 160            // hbox threads (160*4 = 640 >= MAXWP)
#define FIN_T 512           // vbox_fin threads per block

// ---------------- scratch (no allocation allowed: __device__ globals) -------
__device__ float g_h0[NPIX];
__device__ float g_h1[NPIX];
__device__ float g_h2[NPIX];
__device__ float g_h3[NPIX];
__device__ float g_a[NPIX];
__device__ float g_b[NPIX];
__device__ float g_J[3*NPIX];
__device__ unsigned int g_hist[NBC*NBINS];
__device__ float g_p[NBC*2];      // p_low, p_high per (b,c)

__device__ __forceinline__ int reflW(int j){ j = j < 0 ? -j : j; return j >= Wn ? 2*Wn - 2 - j : j; }
__device__ __forceinline__ int reflH(int j){ j = j < 0 ? -j : j; return j >= Hn ? 2*Hn - 2 - j : j; }
__device__ __forceinline__ int get_r(const int* rp){ int r = rp[0]; if (r < 1) r = 1; if (r > RMAX) r = RMAX; return r; }

__device__ __forceinline__ float4 f4add(float4 a, float4 b){ return make_float4(a.x+b.x,a.y+b.y,a.z+b.z,a.w+b.w); }
__device__ __forceinline__ float4 f4sub(float4 a, float4 b){ return make_float4(a.x-b.x,a.y-b.y,a.z-b.z,a.w-b.w); }
__device__ __forceinline__ float2 f2add(float2 a, float2 b){ return make_float2(a.x+b.x,a.y+b.y); }
__device__ __forceinline__ float2 f2sub(float2 a, float2 b){ return make_float2(a.x-b.x,a.y-b.y); }

// ---------------- warp shuffle scans ---------------------------------------
__device__ __forceinline__ float4 wscan4(float4 x, int lane)
{
    #pragma unroll
    for (int d = 1; d < 32; d <<= 1) {
        float a = __shfl_up_sync(0xFFFFFFFFu, x.x, d);
        float b = __shfl_up_sync(0xFFFFFFFFu, x.y, d);
        float c = __shfl_up_sync(0xFFFFFFFFu, x.z, d);
        float e = __shfl_up_sync(0xFFFFFFFFu, x.w, d);
        if (lane >= d) { x.x += a; x.y += b; x.z += c; x.w += e; }
    }
    return x;
}
__device__ __forceinline__ float2 wscan2(float2 x, int lane)
{
    #pragma unroll
    for (int d = 1; d < 32; d <<= 1) {
        float a = __shfl_up_sync(0xFFFFFFFFu, x.x, d);
        float b = __shfl_up_sync(0xFFFFFFFFu, x.y, d);
        if (lane >= d) { x.x += a; x.y += b; }
    }
    return x;
}

// ---------------- K1: staged gray/tg rows + horizontal box -----------------
__global__ void k_hbox4(const int* __restrict__ rp,
                        const float* __restrict__ img,
                        const float* __restrict__ omega,
                        const float* __restrict__ atm)
{
    int r = get_r(rp);
    int Wp = Wn + 2*r;
    int row = blockIdx.x;
    int b = row >> 9, y = row & 511;
    int base = (b << 18) + (y << 9);
    const float* ib = img + (size_t)b * 3 * HWn;
    float om  = omega[b];
    float ra0 = 1.0f / (atm[b*3+0] + 1e-8f);
    float ra1 = 1.0f / (atm[b*3+1] + 1e-8f);
    float ra2 = 1.0f / (atm[b*3+2] + 1e-8f);
    int tid = threadIdx.x;
    int lane = tid & 31, wp = tid >> 5;

    __shared__ float4 P[MAXWP];
    __shared__ float4 wtot[HB_T/32];
    __shared__ float sh_gray[Wn];
    __shared__ float sh_t0a[Wn];   // row y-1 (or y if y==0)
    __shared__ float sh_t0b[Wn];   // row y
    __shared__ float sh_tg[Wn];

    int yy = (y > 0) ? (y - 1) : 0;
    // stage rows: img row y -> gray + t0b ; img row yy -> t0a
    for (int j = tid; j < Wn; j += HB_T) {
        int pix = (y << 9) + j;
        float i0 = ib[pix], i1 = ib[HWn + pix], i2 = ib[2*HWn + pix];
        sh_gray[j] = 0.299f*i0 + 0.587f*i1 + 0.114f*i2;
        sh_t0b[j] = 1.0f - om * fminf(i0*ra0, fminf(i1*ra1, i2*ra2));
        int piy = (yy << 9) + j;
        float a0 = ib[piy], a1 = ib[HWn + piy], a2 = ib[2*HWn + piy];
        sh_t0a[j] = 1.0f - om * fminf(a0*ra0, fminf(a1*ra1, a2*ra2));
    }
    __syncthreads();
    for (int j = tid; j < Wn; j += HB_T) {
        float t_yy_x = sh_t0a[j];
        float txv;
        if (j == 0) txv = t_yy_x;
        else {
            float tm = sh_t0a[j-1];
            txv = tm * __expf(-fabsf(t_yy_x - tm));
        }
        float tg;
        if (y == 0) tg = txv;
        else        tg = txv * __expf(-fabsf(sh_t0b[j] - t_yy_x));
        sh_tg[j] = tg;
    }
    __syncthreads();

    float4 loc[4];
    float4 run = make_float4(0.f,0.f,0.f,0.f);
    #pragma unroll
    for (int q = 0; q < 4; q++) {
        int i = tid * 4 + q;
        float4 v = make_float4(0.f,0.f,0.f,0.f);
        if (i < Wp) {
            int j = reflW(i - r);
            float g = sh_gray[j];
            float t = sh_tg[j];
            v = make_float4(g, t, g*t, g*g);
        }
        run = f4add(run, v);
        loc[q] = run;
    }
    float4 tot = run;
    float4 sc = wscan4(tot, lane);
    float4 excl = f4sub(sc, tot);
    if (lane == 31) wtot[wp] = sc;
    __syncthreads();
    float4 woff = make_float4(0.f,0.f,0.f,0.f);
    #pragma unroll
    for (int w = 0; w < HB_T/32; w++)
        if (w < wp) woff = f4add(woff, wtot[w]);
    float4 off = f4add(excl, woff);
    #pragma unroll
    for (int q = 0; q < 4; q++) {
        int i = tid * 4 + q;
        if (i < Wp) P[i] = f4add(loc[q], off);
    }
    __syncthreads();
    for (int t = tid; t < Wn; t += HB_T) {
        float4 s1 = P[t + 2*r];
        float4 s0 = (t > 0) ? P[t - 1] : make_float4(0.f,0.f,0.f,0.f);
        g_h0[base+t] = s1.x - s0.x;
        g_h1[base+t] = s1.y - s0.y;
        g_h2[base+t] = s1.z - s0.z;
        g_h3[base+t] = s1.w - s0.w;
    }
}

// ---------------- K2: vertical box (4 fields) + a,b  (8-row segments) ------
__global__ void k_vbox_ab(const int* __restrict__ rp)
{
    int r = get_r(rp);
    float invk2 = 1.0f / (float)((2*r+1)*(2*r+1));
    int t = blockIdx.x * blockDim.x + threadIdx.x;
    if (t >= Bn * Wn * NSEG) return;
    int x   = t & 511;
    int seg = (t >> 9) & (NSEG - 1);
    int b   = t >> 15;
    int base = b << 18;
    int y0 = seg * SEG;

    float s0 = 0.f, s1 = 0.f, s2 = 0.f, s3 = 0.f;
    for (int d = -r; d <= r; d++) {
        int j = reflH(y0 + d);
        int o = base + (j << 9) + x;
        s0 += g_h0[o]; s1 += g_h1[o]; s2 += g_h2[o]; s3 += g_h3[o];
    }
    #pragma unroll
    for (int yy = 0; yy < SEG; yy++) {
        int y = y0 + yy;
        int o = base + (y << 9) + x;
        float mI  = s0 * invk2, mp = s1 * invk2;
        float mIp = s2 * invk2, mII = s3 * invk2;
        float a  = (mIp - mI*mp) / (mII - mI*mI + 0.5f);
        float bb = mp - a * mI;
        g_a[o] = a;
        g_b[o] = bb;
        if (yy < SEG - 1) {
            int ja = reflH(y + 1 + r);
            int js = reflH(y - r);
            int oa = base + (ja << 9) + x;
            int os = base + (js << 9) + x;
            s0 += g_h0[oa] - g_h0[os];
            s1 += g_h1[oa] - g_h1[os];
            s2 += g_h2[oa] - g_h2[os];
            s3 += g_h3[oa] - g_h3[os];
        }
    }
}

// ---------------- K3: horizontal box of a,b (+ zero g_hist) ----------------
__global__ void k_hbox2(const int* __restrict__ rp)
{
    // piggyback: zero the coarse histograms (needed before k_vbox_fin)
    {
        int zb = blockIdx.x * 24 + threadIdx.x;   // 4096 blocks * 24 = 98304
        if (threadIdx.x < 24 && zb < NBC*NBINS) g_hist[zb] = 0u;
    }

    int r = get_r(rp);
    int Wp = Wn + 2*r;
    int row = blockIdx.x;
    int b = row >> 9, y = row & 511;
    int base = (b << 18) + (y << 9);
    int tid = threadIdx.x;
    int lane = tid & 31, wp = tid >> 5;

    __shared__ float2 P[MAXWP];
    __shared__ float2 wtot[HB_T/32];

    float2 loc[4];
    float2 run = make_float2(0.f,0.f);
    #pragma unroll
    for (int q = 0; q < 4; q++) {
        int i = tid * 4 + q;
        float2 v = make_float2(0.f,0.f);
        if (i < Wp) {
            int j = reflW(i - r);
            v = make_float2(g_a[base + j], g_b[base + j]);
        }
        run = f2add(run, v);
        loc[q] = run;
    }
    float2 tot = run;
    float2 sc = wscan2(tot, lane);
    float2 excl = f2sub(sc, tot);
    if (lane == 31) wtot[wp] = sc;
    __syncthreads();
    float2 woff = make_float2(0.f,0.f);
    #pragma unroll
    for (int w = 0; w < HB_T/32; w++)
        if (w < wp) woff = f2add(woff, wtot[w]);
    float2 off = f2add(excl, woff);
    #pragma unroll
    for (int q = 0; q < 4; q++) {
        int i = tid * 4 + q;
        if (i < Wp) P[i] = f2add(loc[q], off);
    }
    __syncthreads();
    for (int t = tid; t < Wn; t += HB_T) {
        float2 s1 = P[t + 2*r];
        float2 s0 = (t > 0) ? P[t - 1] : make_float2(0.f,0.f);
        g_h0[base+t] = s1.x - s0.x;
        g_h1[base+t] = s1.y - s0.y;
    }
}

// ---------------- K4: vertical box a,b + t_final + J + fused histogram -----
__global__ void k_vbox_fin(const int* __restrict__ rp,
                           const float* __restrict__ img,
                           const float* __restrict__ atm)
{
    __shared__ unsigned int h3[3*NBINS];        // 48KB: per-channel histograms
    for (int i = threadIdx.x; i < 3*NBINS; i += FIN_T) h3[i] = 0u;
    __syncthreads();

    int r = get_r(rp);
    float invk2 = 1.0f / (float)((2*r+1)*(2*r+1));
    int t = blockIdx.x * FIN_T + threadIdx.x;   // block: one (b,seg), all 512 x
    int x   = t & 511;
    int seg = (t >> 9) & (NSEG - 1);
    int b   = t >> 15;
    int base = b << 18;
    int y0 = seg * SEG;
    float A0 = atm[b*3+0], A1 = atm[b*3+1], A2 = atm[b*3+2];
    const float* ib = img + (size_t)b * 3 * HWn;

    float sa = 0.f, sb = 0.f;
    for (int d = -r; d <= r; d++) {
        int j = reflH(y0 + d);
        int o = base + (j << 9) + x;
        sa += g_h0[o]; sb += g_h1[o];
    }
    #pragma unroll
    for (int yy = 0; yy < SEG; yy++) {
        int y = y0 + yy;
        int pix = (y << 9) + x;
        float ma = sa * invk2, mb = sb * invk2;
        float i0 = ib[pix], i1 = ib[HWn + pix], i2 = ib[2*HWn + pix];
        float g = 0.299f*i0 + 0.587f*i1 + 0.114f*i2;
        float tf = fminf(fmaxf(ma * g + mb, 0.1f), 1.0f);
        float inv_t = 1.0f / (tf + 1e-8f);
        float J0 = fminf(fmaxf((i0 - A0) * inv_t + A0, 0.0f), 1.0f);
        float J1 = fminf(fmaxf((i1 - A1) * inv_t + A1, 0.0f), 1.0f);
        float J2 = fminf(fmaxf((i2 - A2) * inv_t + A2, 0.0f), 1.0f);
        g_J[(b*3+0)*HWn + pix] = J0;
        g_J[(b*3+1)*HWn + pix] = J1;
        g_J[(b*3+2)*HWn + pix] = J2;
        atomicAdd(&h3[           min((int)(J0*4096.0f), 4095)], 1u);
        atomicAdd(&h3[NBINS    + min((int)(J1*4096.0f), 4095)], 1u);
        atomicAdd(&h3[2*NBINS  + min((int)(J2*4096.0f), 4095)], 1u);
        if (yy < SEG - 1) {
            int ja = reflH(y + 1 + r);
            int js = reflH(y - r);
            sa += g_h0[base + (ja << 9) + x] - g_h0[base + (js << 9) + x];
            sb += g_h1[base + (ja << 9) + x] - g_h1[base + (js << 9) + x];
        }
    }
    __syncthreads();
    // flush to global: bc = b*3 + c
    for (int i = threadIdx.x; i < 3*NBINS; i += FIN_T) {
        unsigned int c = h3[i];
        if (c) atomicAdd(&g_hist[b*3*NBINS + i], c);
    }
}

// ---------------- K5: percentiles via interpolated order statistics --------
__device__ void find_kth_interp(const unsigned int* __restrict__ hist,
                                const unsigned int* __restrict__ ps,
                                unsigned int target, float* pval)
{
    unsigned int cum = 0;
    for (int t = 0; t < 128; t++) {
        unsigned int s = ps[t];
        if (cum + s > target) {
            unsigned int c2 = cum;
            for (int i = t*32; ; i++) {
                unsigned int c = hist[i];
                if (c2 + c > target) {
                    float frac = ((float)(target - c2) + 0.5f) / (float)c;
                    *pval = ((float)i + frac) * (1.0f/4096.0f);
                    return;
                }
                c2 += c;
            }
        }
        cum += s;
    }
    *pval = 1.0f;
}

__global__ void k_sel(const float* __restrict__ Ll, const float* __restrict__ Lh)
{
    int bc = blockIdx.x;
    int b = bc / 3;
    const unsigned int* hb = g_hist + bc * NBINS;
    __shared__ unsigned int ps[128];
    unsigned int s = 0;
    for (int i = threadIdx.x * 32; i < threadIdx.x * 32 + 32; i++) s += hb[i];
    ps[threadIdx.x] = s;
    __syncthreads();
    if (threadIdx.x == 0) {
        const int n = HWn;
        float tl = (Ll[b] / 100.0f) * (float)n;
        float th = (Lh[b] / 100.0f) * (float)n;
        int li = (int)tl; if (li < 0) li = 0; if (li > n-1) li = n-1;
        int hi = (int)th; if (hi < 0) hi = 0; if (hi > n-1) hi = n-1;
        float pl, ph;
        find_kth_interp(hb, ps, (unsigned int)li, &pl);
        find_kth_interp(hb, ps, (unsigned int)hi, &ph);
        g_p[bc*2+0] = pl;
        g_p[bc*2+1] = ph;
    }
}

// ---------------- K6: final stretch (pointwise, float4) --------------------
__global__ void k_final(float4* __restrict__ out)
{
    int idx = blockIdx.x * blockDim.x + threadIdx.x;
    if (idx >= 3*NPIX/4) return;
    int bc = idx >> 16;
    float pl = g_p[bc*2+0];
    float ph = g_p[bc*2+1];
    float inv = 1.0f / (ph - pl + 1e-8f);
    const float4* J4 = reinterpret_cast<const float4*>(g_J);
    float4 v = J4[idx];
    float4 o;
    o.x = fminf(fmaxf((fminf(fmaxf(v.x, pl), ph) - pl) * inv, 0.0f), 1.0f);
    o.y = fminf(fmaxf((fminf(fmaxf(v.y, pl), ph) - pl) * inv, 0.0f), 1.0f);
    o.z = fminf(fmaxf((fminf(fmaxf(v.z, pl), ph) - pl) * inv, 0.0f), 1.0f);
    o.w = fminf(fmaxf((fminf(fmaxf(v.w, pl), ph) - pl) * inv, 0.0f), 1.0f);
    out[idx] = o;
}

// ---------------- launch ----------------------------------------------------
extern "C" void kernel_launch(void* const* d_in, const int* in_sizes, int n_in,
                              void* d_out, int out_size)
{
    const float* img   = (const float*)d_in[0];
    const float* omega = (const float*)d_in[1];
    const float* atm   = (const float*)d_in[2];
    const float* Ll    = (const float*)d_in[3];
    const float* Lh    = (const float*)d_in[4];
    const int*   rp    = (const int*)  d_in[5];
    float4* out = (float4*)d_out;

    k_hbox4<<<Bn*Hn, HB_T>>>(rp, img, omega, atm);
    k_vbox_ab<<<(Bn*Wn*NSEG)/256, 256>>>(rp);
    k_hbox2<<<Bn*Hn, HB_T>>>(rp);
    k_vbox_fin<<<(Bn*Wn*NSEG)/FIN_T, FIN_T>>>(rp, img, atm);
    k_sel<<<NBC, 128>>>(Ll, Lh);
    k_final<<<(3*NPIX/4 + 255)/256, 256>>>(out);
}

// round 11
// speedup vs baseline: 3.1080x; 1.0991x over previous
#include <cuda_runtime.h>

#define Bn   8
#define Hn   512
#define Wn   512
#define HWn  (Hn*Wn)        // 262144
#define NPIX (Bn*HWn)       // 2097152
#define NBC  24             // B*3 (b,c) pairs
#define NBINS 2048
#define RMAX 50
#define MAXWP (Wn + 2*RMAX) // 612
#define SEG  8              // rows per thread in vertical passes
#define NSEG (Hn/SEG)       // 64
#define HB_T 160            // hbox threads (160*4 = 640 >= MAXWP)
#define VH_T 512            // fused vbox_ab+hbox2 threads
#define FIN_T 512           // vbox_fin threads per block

// ---------------- scratch (no allocation allowed: __device__ globals) -------
__device__ float g_h0[NPIX];
__device__ float g_h1[NPIX];
__device__ float g_h2[NPIX];
__device__ float g_h3[NPIX];
__device__ float g_J[3*NPIX];
__device__ unsigned int g_hist[NBC*NBINS];
__device__ float g_p[NBC*2];      // p_low, p_high per (b,c)

__device__ __forceinline__ int reflW(int j){ j = j < 0 ? -j : j; return j >= Wn ? 2*Wn - 2 - j : j; }
__device__ __forceinline__ int reflH(int j){ j = j < 0 ? -j : j; return j >= Hn ? 2*Hn - 2 - j : j; }
__device__ __forceinline__ int get_r(const int* rp){ int r = rp[0]; if (r < 1) r = 1; if (r > RMAX) r = RMAX; return r; }

__device__ __forceinline__ float4 f4add(float4 a, float4 b){ return make_float4(a.x+b.x,a.y+b.y,a.z+b.z,a.w+b.w); }
__device__ __forceinline__ float4 f4sub(float4 a, float4 b){ return make_float4(a.x-b.x,a.y-b.y,a.z-b.z,a.w-b.w); }
__device__ __forceinline__ float2 f2add(float2 a, float2 b){ return make_float2(a.x+b.x,a.y+b.y); }
__device__ __forceinline__ float2 f2sub(float2 a, float2 b){ return make_float2(a.x-b.x,a.y-b.y); }

// ---------------- warp shuffle scans ---------------------------------------
__device__ __forceinline__ float4 wscan4(float4 x, int lane)
{
    #pragma unroll
    for (int d = 1; d < 32; d <<= 1) {
        float a = __shfl_up_sync(0xFFFFFFFFu, x.x, d);
        float b = __shfl_up_sync(0xFFFFFFFFu, x.y, d);
        float c = __shfl_up_sync(0xFFFFFFFFu, x.z, d);
        float e = __shfl_up_sync(0xFFFFFFFFu, x.w, d);
        if (lane >= d) { x.x += a; x.y += b; x.z += c; x.w += e; }
    }
    return x;
}
__device__ __forceinline__ float2 wscan2(float2 x, int lane)
{
    #pragma unroll
    for (int d = 1; d < 32; d <<= 1) {
        float a = __shfl_up_sync(0xFFFFFFFFu, x.x, d);
        float b = __shfl_up_sync(0xFFFFFFFFu, x.y, d);
        if (lane >= d) { x.x += a; x.y += b; }
    }
    return x;
}

// ---------------- K1: staged gray/tg rows + horizontal box (+zero hist) ----
__global__ void k_hbox4(const int* __restrict__ rp,
                        const float* __restrict__ img,
                        const float* __restrict__ omega,
                        const float* __restrict__ atm)
{
    // piggyback: zero coarse histograms (4096 blocks * 12 = 49152 = 24*2048)
    if (threadIdx.x < 12) g_hist[blockIdx.x * 12 + threadIdx.x] = 0u;

    int r = get_r(rp);
    int Wp = Wn + 2*r;
    int row = blockIdx.x;
    int b = row >> 9, y = row & 511;
    int base = (b << 18) + (y << 9);
    const float* ib = img + (size_t)b * 3 * HWn;
    float om  = omega[b];
    float ra0 = 1.0f / (atm[b*3+0] + 1e-8f);
    float ra1 = 1.0f / (atm[b*3+1] + 1e-8f);
    float ra2 = 1.0f / (atm[b*3+2] + 1e-8f);
    int tid = threadIdx.x;
    int lane = tid & 31, wp = tid >> 5;

    __shared__ float4 P[MAXWP];
    __shared__ float4 wtot[HB_T/32];
    __shared__ float sh_gray[Wn];
    __shared__ float sh_t0a[Wn];   // row y-1 (or y if y==0)
    __shared__ float sh_t0b[Wn];   // row y
    __shared__ float sh_tg[Wn];

    int yy = (y > 0) ? (y - 1) : 0;
    for (int j = tid; j < Wn; j += HB_T) {
        int pix = (y << 9) + j;
        float i0 = ib[pix], i1 = ib[HWn + pix], i2 = ib[2*HWn + pix];
        sh_gray[j] = 0.299f*i0 + 0.587f*i1 + 0.114f*i2;
        sh_t0b[j] = 1.0f - om * fminf(i0*ra0, fminf(i1*ra1, i2*ra2));
        int piy = (yy << 9) + j;
        float a0 = ib[piy], a1 = ib[HWn + piy], a2 = ib[2*HWn + piy];
        sh_t0a[j] = 1.0f - om * fminf(a0*ra0, fminf(a1*ra1, a2*ra2));
    }
    __syncthreads();
    for (int j = tid; j < Wn; j += HB_T) {
        float t_yy_x = sh_t0a[j];
        float txv;
        if (j == 0) txv = t_yy_x;
        else {
            float tm = sh_t0a[j-1];
            txv = tm * __expf(-fabsf(t_yy_x - tm));
        }
        float tg;
        if (y == 0) tg = txv;
        else        tg = txv * __expf(-fabsf(sh_t0b[j] - t_yy_x));
        sh_tg[j] = tg;
    }
    __syncthreads();

    float4 loc[4];
    float4 run = make_float4(0.f,0.f,0.f,0.f);
    #pragma unroll
    for (int q = 0; q < 4; q++) {
        int i = tid * 4 + q;
        float4 v = make_float4(0.f,0.f,0.f,0.f);
        if (i < Wp) {
            int j = reflW(i - r);
            float g = sh_gray[j];
            float t = sh_tg[j];
            v = make_float4(g, t, g*t, g*g);
        }
        run = f4add(run, v);
        loc[q] = run;
    }
    float4 tot = run;
    float4 sc = wscan4(tot, lane);
    float4 excl = f4sub(sc, tot);
    if (lane == 31) wtot[wp] = sc;
    __syncthreads();
    float4 woff = make_float4(0.f,0.f,0.f,0.f);
    #pragma unroll
    for (int w = 0; w < HB_T/32; w++)
        if (w < wp) woff = f4add(woff, wtot[w]);
    float4 off = f4add(excl, woff);
    #pragma unroll
    for (int q = 0; q < 4; q++) {
        int i = tid * 4 + q;
        if (i < Wp) P[i] = f4add(loc[q], off);
    }
    __syncthreads();
    for (int t = tid; t < Wn; t += HB_T) {
        float4 s1 = P[t + 2*r];
        float4 s0 = (t > 0) ? P[t - 1] : make_float4(0.f,0.f,0.f,0.f);
        g_h0[base+t] = s1.x - s0.x;
        g_h1[base+t] = s1.y - s0.y;
        g_h2[base+t] = s1.z - s0.z;
        g_h3[base+t] = s1.w - s0.w;
    }
}

// ---------------- K2: fused V1(4 fields)+a,b + H2 row scan -----------------
// block = one (b, seg): 512 threads, one per column. a,b stay in shared.
__global__ void __launch_bounds__(VH_T) k_vh(const int* __restrict__ rp)
{
    int r = get_r(rp);
    int Wp = Wn + 2*r;
    float invk2 = 1.0f / (float)((2*r+1)*(2*r+1));
    int bs = blockIdx.x;            // 0..Bn*NSEG-1
    int b   = bs >> 6;              // NSEG = 64
    int seg = bs & (NSEG - 1);
    int y0 = seg * SEG;
    int x = threadIdx.x;
    int base = b << 18;
    int lane = x & 31, wpid = x >> 5;

    __shared__ float sa8[SEG][Wn];
    __shared__ float sb8[SEG][Wn];
    __shared__ float2 P[MAXWP];
    __shared__ float2 wtot[VH_T/32];

    // ---- V1: window sums of h0..h3, produce a,b into shared ----
    {
        float s0 = 0.f, s1 = 0.f, s2 = 0.f, s3 = 0.f;
        bool interior = (y0 >= r) && (y0 + SEG - 1 + r < Hn);
        if (interior) {
            int o = base + ((y0 - r) << 9) + x;
            for (int d = 0; d <= 2*r; d++) {
                s0 += g_h0[o]; s1 += g_h1[o]; s2 += g_h2[o]; s3 += g_h3[o];
                o += Wn;
            }
            int oa = base + ((y0 + 1 + r) << 9) + x;  // row to add
            int os = base + ((y0 - r) << 9) + x;      // row to subtract
            #pragma unroll
            for (int yy = 0; yy < SEG; yy++) {
                float mI  = s0 * invk2, mp = s1 * invk2;
                float mIp = s2 * invk2, mII = s3 * invk2;
                float a  = (mIp - mI*mp) / (mII - mI*mI + 0.5f);
                sa8[yy][x] = a;
                sb8[yy][x] = mp - a * mI;
                if (yy < SEG - 1) {
                    s0 += g_h0[oa] - g_h0[os];
                    s1 += g_h1[oa] - g_h1[os];
                    s2 += g_h2[oa] - g_h2[os];
                    s3 += g_h3[oa] - g_h3[os];
                    oa += Wn; os += Wn;
                }
            }
        } else {
            for (int d = -r; d <= r; d++) {
                int j = reflH(y0 + d);
                int o = base + (j << 9) + x;
                s0 += g_h0[o]; s1 += g_h1[o]; s2 += g_h2[o]; s3 += g_h3[o];
            }
            #pragma unroll
            for (int yy = 0; yy < SEG; yy++) {
                int y = y0 + yy;
                float mI  = s0 * invk2, mp = s1 * invk2;
                float mIp = s2 * invk2, mII = s3 * invk2;
                float a  = (mIp - mI*mp) / (mII - mI*mI + 0.5f);
                sa8[yy][x] = a;
                sb8[yy][x] = mp - a * mI;
                if (yy < SEG - 1) {
                    int ja = reflH(y + 1 + r);
                    int js = reflH(y - r);
                    int oa = base + (ja << 9) + x;
                    int os = base + (js << 9) + x;
                    s0 += g_h0[oa] - g_h0[os];
                    s1 += g_h1[oa] - g_h1[os];
                    s2 += g_h2[oa] - g_h2[os];
                    s3 += g_h3[oa] - g_h3[os];
                }
            }
        }
    }
    __syncthreads();

    // ---- H2: row scans of a,b (2 padded elems per thread) ----
    for (int yy = 0; yy < SEG; yy++) {
        int i0 = 2*x, i1 = 2*x + 1;
        float2 v0 = make_float2(0.f,0.f), v1 = make_float2(0.f,0.f);
        if (i0 < Wp) {
            int j = reflW(i0 - r);
            v0 = make_float2(sa8[yy][j], sb8[yy][j]);
        }
        if (i1 < Wp) {
            int j = reflW(i1 - r);
            v1 = make_float2(sa8[yy][j], sb8[yy][j]);
        }
        float2 run = f2add(v0, v1);
        float2 sc = wscan2(run, lane);
        float2 excl = f2sub(sc, run);
        if (lane == 31) wtot[wpid] = sc;
        __syncthreads();
        float2 woff = make_float2(0.f,0.f);
        #pragma unroll
        for (int w = 0; w < VH_T/32; w++)
            if (w < wpid) woff = f2add(woff, wtot[w]);
        float2 off = f2add(excl, woff);
        if (i0 < Wp) P[i0] = f2add(off, v0);
        if (i1 < Wp) P[i1] = f2add(f2add(off, v0), v1);
        __syncthreads();
        int y = y0 + yy;
        float2 s1 = P[x + 2*r];
        float2 s0 = (x > 0) ? P[x - 1] : make_float2(0.f,0.f);
        g_h0[base + (y << 9) + x] = s1.x - s0.x;
        g_h1[base + (y << 9) + x] = s1.y - s0.y;
        // next iteration's wtot/P writes are ordered by the two syncs above
    }
}

// ---------------- K3: vertical box a,b + t_final + J + fused histogram -----
__global__ void k_vbox_fin(const int* __restrict__ rp,
                           const float* __restrict__ img,
                           const float* __restrict__ atm)
{
    __shared__ unsigned int h3[3*NBINS];        // 24KB: per-channel histograms
    for (int i = threadIdx.x; i < 3*NBINS; i += FIN_T) h3[i] = 0u;
    __syncthreads();

    int r = get_r(rp);
    float invk2 = 1.0f / (float)((2*r+1)*(2*r+1));
    int t = blockIdx.x * FIN_T + threadIdx.x;
    int x   = t & 511;
    int seg = (t >> 9) & (NSEG - 1);
    int b   = t >> 15;
    int base = b << 18;
    int y0 = seg * SEG;
    float A0 = atm[b*3+0], A1 = atm[b*3+1], A2 = atm[b*3+2];
    const float* ib = img + (size_t)b * 3 * HWn;

    float sa = 0.f, sb = 0.f;
    bool interior = (y0 >= r) && (y0 + SEG - 1 + r < Hn);
    int oa, os;
    if (interior) {
        int o = base + ((y0 - r) << 9) + x;
        for (int d = 0; d <= 2*r; d++) { sa += g_h0[o]; sb += g_h1[o]; o += Wn; }
        oa = base + ((y0 + 1 + r) << 9) + x;
        os = base + ((y0 - r) << 9) + x;
    } else {
        for (int d = -r; d <= r; d++) {
            int j = reflH(y0 + d);
            int o = base + (j << 9) + x;
            sa += g_h0[o]; sb += g_h1[o];
        }
        oa = os = 0;
    }
    #pragma unroll
    for (int yy = 0; yy < SEG; yy++) {
        int y = y0 + yy;
        int pix = (y << 9) + x;
        float ma = sa * invk2, mb = sb * invk2;
        float i0 = ib[pix], i1 = ib[HWn + pix], i2 = ib[2*HWn + pix];
        float g = 0.299f*i0 + 0.587f*i1 + 0.114f*i2;
        float tf = fminf(fmaxf(ma * g + mb, 0.1f), 1.0f);
        float inv_t = __fdividef(1.0f, tf + 1e-8f);
        float J0 = fminf(fmaxf((i0 - A0) * inv_t + A0, 0.0f), 1.0f);
        float J1 = fminf(fmaxf((i1 - A1) * inv_t + A1, 0.0f), 1.0f);
        float J2 = fminf(fmaxf((i2 - A2) * inv_t + A2, 0.0f), 1.0f);
        g_J[(b*3+0)*HWn + pix] = J0;
        g_J[(b*3+1)*HWn + pix] = J1;
        g_J[(b*3+2)*HWn + pix] = J2;
        atomicAdd(&h3[          min((int)(J0*(float)NBINS), NBINS-1)], 1u);
        atomicAdd(&h3[NBINS   + min((int)(J1*(float)NBINS), NBINS-1)], 1u);
        atomicAdd(&h3[2*NBINS + min((int)(J2*(float)NBINS), NBINS-1)], 1u);
        if (yy < SEG - 1) {
            if (interior) {
                sa += g_h0[oa] - g_h0[os];
                sb += g_h1[oa] - g_h1[os];
                oa += Wn; os += Wn;
            } else {
                int ja = reflH(y + 1 + r);
                int js = reflH(y - r);
                sa += g_h0[base + (ja << 9) + x] - g_h0[base + (js << 9) + x];
                sb += g_h1[base + (ja << 9) + x] - g_h1[base + (js << 9) + x];
            }
        }
    }
    __syncthreads();
    for (int i = threadIdx.x; i < 3*NBINS; i += FIN_T) {
        unsigned int c = h3[i];
        if (c) atomicAdd(&g_hist[b*3*NBINS + i], c);
    }
}

// ---------------- K4: percentiles via interpolated order statistics --------
__device__ void find_kth_interp(const unsigned int* __restrict__ hist,
                                const unsigned int* __restrict__ ps,
                                unsigned int target, float* pval)
{
    unsigned int cum = 0;
    for (int t = 0; t < 128; t++) {
        unsigned int s = ps[t];
        if (cum + s > target) {
            unsigned int c2 = cum;
            for (int i = t*16; ; i++) {
                unsigned int c = hist[i];
                if (c2 + c > target) {
                    float frac = ((float)(target - c2) + 0.5f) / (float)c;
                    *pval = ((float)i + frac) * (1.0f/(float)NBINS);
                    return;
                }
                c2 += c;
            }
        }
        cum += s;
    }
    *pval = 1.0f;
}

__global__ void k_sel(const float* __restrict__ Ll, const float* __restrict__ Lh)
{
    int bc = blockIdx.x;
    int b = bc / 3;
    const unsigned int* hb = g_hist + bc * NBINS;
    __shared__ unsigned int ps[128];
    unsigned int s = 0;
    for (int i = threadIdx.x * 16; i < threadIdx.x * 16 + 16; i++) s += hb[i];
    ps[threadIdx.x] = s;
    __syncthreads();
    if (threadIdx.x == 0) {
        const int n = HWn;
        float tl = (Ll[b] / 100.0f) * (float)n;
        float th = (Lh[b] / 100.0f) * (float)n;
        int li = (int)tl; if (li < 0) li = 0; if (li > n-1) li = n-1;
        int hi = (int)th; if (hi < 0) hi = 0; if (hi > n-1) hi = n-1;
        float pl, ph;
        find_kth_interp(hb, ps, (unsigned int)li, &pl);
        find_kth_interp(hb, ps, (unsigned int)hi, &ph);
        g_p[bc*2+0] = pl;
        g_p[bc*2+1] = ph;
    }
}

// ---------------- K5: final stretch (pointwise, float4) --------------------
__global__ void k_final(float4* __restrict__ out)
{
    int idx = blockIdx.x * blockDim.x + threadIdx.x;
    if (idx >= 3*NPIX/4) return;
    int bc = idx >> 16;
    float pl = g_p[bc*2+0];
    float ph = g_p[bc*2+1];
    float inv = __fdividef(1.0f, ph - pl + 1e-8f);
    const float4* J4 = reinterpret_cast<const float4*>(g_J);
    float4 v = J4[idx];
    float4 o;
    o.x = fminf(fmaxf((fminf(fmaxf(v.x, pl), ph) - pl) * inv, 0.0f), 1.0f);
    o.y = fminf(fmaxf((fminf(fmaxf(v.y, pl), ph) - pl) * inv, 0.0f), 1.0f);
    o.z = fminf(fmaxf((fminf(fmaxf(v.z, pl), ph) - pl) * inv, 0.0f), 1.0f);
    o.w = fminf(fmaxf((fminf(fmaxf(v.w, pl), ph) - pl) * inv, 0.0f), 1.0f);
    out[idx] = o;
}

// ---------------- launch ----------------------------------------------------
extern "C" void kernel_launch(void* const* d_in, const int* in_sizes, int n_in,
                              void* d_out, int out_size)
{
    const float* img   = (const float*)d_in[0];
    const float* omega = (const float*)d_in[1];
    const float* atm   = (const float*)d_in[2];
    const float* Ll    = (const float*)d_in[3];
    const float* Lh    = (const float*)d_in[4];
    const int*   rp    = (const int*)  d_in[5];
    float4* out = (float4*)d_out;

    k_hbox4<<<Bn*Hn, HB_T>>>(rp, img, omega, atm);
    k_vh<<<Bn*NSEG, VH_T>>>(rp);
    k_vbox_fin<<<(Bn*Wn*NSEG)/FIN_T, FIN_T>>>(rp, img, atm);
    k_sel<<<NBC, 128>>>(Ll, Lh);
    k_final<<<(3*NPIX/4 + 255)/256, 256>>>(out);
}